// round 2
// baseline (speedup 1.0000x reference)
#include <cuda_runtime.h>
#include <math.h>

#define TSEQ 2048
#define DIM  1024
#define NH   16
#define HD   64

// ---- scratch (no allocs allowed) ----
__device__ float g_Wqkv[3 * DIM * DIM];   // scaled qkv weight, [3072][1024]
__device__ float g_qkv [TSEQ * 3 * DIM];  // raw qkv projection
__device__ float g_Q   [TSEQ * DIM];      // post norm+rotary, (t,h,d)
__device__ float g_K   [TSEQ * DIM];
__device__ float g_V   [TSEQ * DIM];
__device__ float g_Y   [TSEQ * DIM];      // attention out, pre-scaled by c_proj_scale

__device__ __forceinline__ float softplus_f(float x) { return log1pf(expf(x)); }

// ---------------------------------------------------------------------------
// W_qkv[e][d] = qkv_scale[e] * {c_q|c_k|c_v}[e mod 1024][d]
// ---------------------------------------------------------------------------
__global__ void build_wqkv(const float* __restrict__ cq,
                           const float* __restrict__ ck,
                           const float* __restrict__ cv,
                           const float* __restrict__ scale) {
    int i = blockIdx.x * 256 + threadIdx.x;       // [0, 3072*1024)
    int e = i >> 10;
    int d = i & 1023;
    const float* src = (e < 1024) ? cq : ((e < 2048) ? ck : cv);
    g_Wqkv[i] = scale[e] * src[(e & 1023) * DIM + d];
}

// ---------------------------------------------------------------------------
// C[M,N] = A[M,K] * B[N,K]^T   (all row-major, dims multiples of 64/16)
// 64x64 block tile, BK=16, 4x4 per thread, 256 threads.
// ---------------------------------------------------------------------------
__global__ void sgemm_abt(const float* __restrict__ A,
                          const float* __restrict__ B,
                          float* __restrict__ C,
                          int M, int N, int K) {
    __shared__ float As[64][17];
    __shared__ float Bs[64][17];
    const int tid = threadIdx.x;
    const int tx = tid & 15;          // col group
    const int ty = tid >> 4;          // row group
    const int m0 = blockIdx.y * 64;
    const int n0 = blockIdx.x * 64;

    float acc[4][4] = {};

    for (int k0 = 0; k0 < K; k0 += 16) {
        #pragma unroll
        for (int i = 0; i < 4; i++) {
            int idx = tid + i * 256;          // [0,1024)
            int r = idx >> 4, c = idx & 15;
            As[r][c] = A[(m0 + r) * K + k0 + c];
            Bs[r][c] = B[(n0 + r) * K + k0 + c];
        }
        __syncthreads();
        #pragma unroll
        for (int kk = 0; kk < 16; kk++) {
            float a[4], b[4];
            #pragma unroll
            for (int i = 0; i < 4; i++) a[i] = As[ty * 4 + i][kk];
            #pragma unroll
            for (int j = 0; j < 4; j++) b[j] = Bs[tx * 4 + j][kk];
            #pragma unroll
            for (int i = 0; i < 4; i++)
                #pragma unroll
                for (int j = 0; j < 4; j++)
                    acc[i][j] = fmaf(a[i], b[j], acc[i][j]);
        }
        __syncthreads();
    }
    #pragma unroll
    for (int i = 0; i < 4; i++)
        #pragma unroll
        for (int j = 0; j < 4; j++)
            C[(m0 + ty * 4 + i) * N + n0 + tx * 4 + j] = acc[i][j];
}

// ---------------------------------------------------------------------------
// Per (t,h): v residual, RMS-norm(q,k) over hd=64, rotary. 64 threads/block.
// ---------------------------------------------------------------------------
__global__ void postprocess(const float* __restrict__ qkv,
                            const float* __restrict__ ve,
                            const float* __restrict__ q_scale,
                            const float* __restrict__ k_scale,
                            const float* __restrict__ v_lambda,
                            float* __restrict__ Q,
                            float* __restrict__ Kb,
                            float* __restrict__ V) {
    const int t = blockIdx.x, h = blockIdx.y, d = threadIdx.x;
    __shared__ float sq[64], sk[64];
    __shared__ float redq[2], redk[2];

    const int base  = t * 3 * DIM + h * HD + d;
    const int obase = t * DIM + h * HD + d;
    float q = qkv[base];
    float k = qkv[base + DIM];
    float v = qkv[base + 2 * DIM];

    V[obase] = v + softplus_f(*v_lambda) * ve[obase];

    float qs = q * q, ks = k * k;
    #pragma unroll
    for (int off = 16; off > 0; off >>= 1) {
        qs += __shfl_xor_sync(0xffffffffu, qs, off);
        ks += __shfl_xor_sync(0xffffffffu, ks, off);
    }
    int warp = d >> 5;
    if ((d & 31) == 0) { redq[warp] = qs; redk[warp] = ks; }
    __syncthreads();
    float qsum = redq[0] + redq[1];
    float ksum = redk[0] + redk[1];

    const float EPS = 1.1920929e-07f;  // float32 eps, matches jnp.finfo
    float qn = q * (softplus_f(*q_scale) * 8.0f / (sqrtf(qsum) + EPS));
    float kn = k * (softplus_f(*k_scale) * 8.0f / (sqrtf(ksum) + EPS));
    sq[d] = qn;
    sk[d] = kn;
    __syncthreads();

    if (d < 32) {
        float c = 1.0f, s = 0.0f;
        if (d < 16) {
            float freq  = powf(1.0f / 1024.0f, (float)d * (1.0f / 15.0f));
            float theta = (float)t * freq;
            c = cosf(theta);
            s = sinf(theta);
        }
        float x1q = sq[d], x2q = sq[d + 32];
        float x1k = sk[d], x2k = sk[d + 32];
        int ob = t * DIM + h * HD;
        Q [ob + d]      =  x1q * c + x2q * s;
        Q [ob + d + 32] = -x1q * s + x2q * c;
        Kb[ob + d]      =  x1k * c + x2k * s;
        Kb[ob + d + 32] = -x1k * s + x2k * c;
    }
}

// ---------------------------------------------------------------------------
// Causal flash attention, fp32. One block = (head, 64-query tile), 64 threads,
// one query per thread. K/V/S tiles in 48KB static smem. c_proj_scale is
// folded into the epilogue so the final GEMM is plain.
// ---------------------------------------------------------------------------
__global__ void attn(const float* __restrict__ Q,
                     const float* __restrict__ K,
                     const float* __restrict__ V,
                     const float* __restrict__ c_proj_scale,
                     float* __restrict__ Y) {
    __shared__ float Ks[64][64];
    __shared__ float Vs[64][64];
    __shared__ float Ss[64][64];   // [key][query] -> conflict-free per-lane

    const int h   = blockIdx.y;
    const int q0  = blockIdx.x * 64;
    const int tid = threadIdx.x;
    const int qi  = q0 + tid;

    float qreg[HD];
    #pragma unroll
    for (int d = 0; d < HD; d++) qreg[d] = Q[qi * DIM + h * HD + d];

    float m = -INFINITY, l = 0.0f;
    float acc[HD];
    #pragma unroll
    for (int d = 0; d < HD; d++) acc[d] = 0.0f;

    for (int k0 = 0; k0 <= q0; k0 += 64) {
        for (int i = tid; i < 64 * 64; i += 64) {
            int kk = i >> 6, d = i & 63;
            Ks[kk][d] = K[(k0 + kk) * DIM + h * HD + d];
            Vs[kk][d] = V[(k0 + kk) * DIM + h * HD + d];
        }
        __syncthreads();

        float tmax = -INFINITY;
        for (int kk = 0; kk < 64; kk++) {
            float s;
            if (k0 + kk <= qi) {
                s = 0.0f;
                #pragma unroll
                for (int d = 0; d < HD; d++) s = fmaf(qreg[d], Ks[kk][d], s);
                s *= 0.125f;   // 1/sqrt(64)
            } else {
                s = -INFINITY;
            }
            Ss[kk][tid] = s;
            tmax = fmaxf(tmax, s);
        }

        float mnew = fmaxf(m, tmax);
        float corr = expf(m - mnew);   // m=-inf on first tile -> corr=0
        m = mnew;
        l *= corr;
        #pragma unroll
        for (int d = 0; d < HD; d++) acc[d] *= corr;

        for (int kk = 0; kk < 64; kk++) {
            float p = expf(Ss[kk][tid] - m);  // masked -> exp(-inf)=0
            l += p;
            #pragma unroll
            for (int d = 0; d < HD; d++) acc[d] = fmaf(p, Vs[kk][d], acc[d]);
        }
        __syncthreads();
    }

    float inv = 1.0f / l;
    #pragma unroll
    for (int d = 0; d < HD; d++)
        Y[qi * DIM + h * HD + d] = acc[d] * inv * c_proj_scale[h * HD + d];
}

// ---------------------------------------------------------------------------
extern "C" void kernel_launch(void* const* d_in, const int* in_sizes, int n_in,
                              void* d_out, int out_size) {
    const float* x            = (const float*)d_in[0];
    const float* ve           = (const float*)d_in[1];
    const float* c_q          = (const float*)d_in[2];
    const float* c_k          = (const float*)d_in[3];
    const float* c_v          = (const float*)d_in[4];
    const float* qkv_scale    = (const float*)d_in[5];
    const float* q_scale      = (const float*)d_in[6];
    const float* k_scale      = (const float*)d_in[7];
    const float* v_lambda     = (const float*)d_in[8];
    const float* c_proj       = (const float*)d_in[9];
    const float* c_proj_scale = (const float*)d_in[10];
    float* out = (float*)d_out;

    float *Wqkv, *qkv, *Qb, *Kb, *Vb, *Yb;
    cudaGetSymbolAddress((void**)&Wqkv, g_Wqkv);
    cudaGetSymbolAddress((void**)&qkv,  g_qkv);
    cudaGetSymbolAddress((void**)&Qb,   g_Q);
    cudaGetSymbolAddress((void**)&Kb,   g_K);
    cudaGetSymbolAddress((void**)&Vb,   g_V);
    cudaGetSymbolAddress((void**)&Yb,   g_Y);

    // 1. scaled QKV weight
    build_wqkv<<<(3 * DIM * DIM) / 256, 256>>>(c_q, c_k, c_v, qkv_scale);

    // 2. qkv = x @ Wqkv^T   (2048 x 3072, K=1024)
    {
        dim3 grid(3 * DIM / 64, TSEQ / 64);
        sgemm_abt<<<grid, 256>>>(x, Wqkv, qkv, TSEQ, 3 * DIM, DIM);
    }

    // 3. residual + RMS norm + rotary
    {
        dim3 grid(TSEQ, NH);
        postprocess<<<grid, 64>>>(qkv, ve, q_scale, k_scale, v_lambda, Qb, Kb, Vb);
    }

    // 4. causal attention (c_proj_scale folded into Y)
    {
        dim3 grid(TSEQ / 64, NH);
        attn<<<grid, 64>>>(Qb, Kb, Vb, c_proj_scale, Yb);
    }

    // 5. out = Y @ c_proj^T  (2048 x 1024, K=1024)
    {
        dim3 grid(DIM / 64, TSEQ / 64);
        sgemm_abt<<<grid, 256>>>(Yb, c_proj, out, TSEQ, DIM, DIM);
    }
}

// round 4
// speedup vs baseline: 1.2226x; 1.2226x over previous
#include <cuda_runtime.h>
#include <math.h>

#define TSEQ 2048
#define DIM  1024
#define NH   16
#define HD   64

// ---- scratch (no allocs allowed) ----
__device__ float g_Wqkv[3 * DIM * DIM];
__device__ float g_qkv [TSEQ * 3 * DIM];
__device__ float g_Q   [TSEQ * DIM];
__device__ float g_K   [TSEQ * DIM];
__device__ float g_V   [TSEQ * DIM];
__device__ float g_Y   [TSEQ * DIM];

__device__ __forceinline__ float softplus_f(float x) { return log1pf(expf(x)); }

// ---------------------------------------------------------------------------
__global__ void build_wqkv(const float* __restrict__ cq,
                           const float* __restrict__ ck,
                           const float* __restrict__ cv,
                           const float* __restrict__ scale) {
    int i = blockIdx.x * 256 + threadIdx.x;
    int e = i >> 10;
    int d = i & 1023;
    const float* src = (e < 1024) ? cq : ((e < 2048) ? ck : cv);
    g_Wqkv[i] = scale[e] * src[(e & 1023) * DIM + d];
}

// ---------------------------------------------------------------------------
// C[M,N] = A[M,K] * B[N,K]^T. BM=BN=128, BK=8, TM=TN=8, 256 threads.
// ---------------------------------------------------------------------------
__global__ __launch_bounds__(256) void sgemm128(const float* __restrict__ A,
                                                const float* __restrict__ B,
                                                float* __restrict__ C,
                                                int M, int N, int K) {
    __shared__ float As[8][132];   // [k][m], padded
    __shared__ float Bs[8][132];   // [k][n], padded
    const int tid = threadIdx.x;
    const int m0 = blockIdx.y * 128;
    const int n0 = blockIdx.x * 128;
    const int lr = tid >> 1;            // 0..127 : row within tile
    const int lc = (tid & 1) * 4;       // 0 or 4 : k offset
    const int tx = tid & 15;            // 0..15
    const int ty = tid >> 4;            // 0..15

    float acc[8][8] = {};

    for (int k0 = 0; k0 < K; k0 += 8) {
        float4 av = *(const float4*)&A[(m0 + lr) * K + k0 + lc];
        float4 bv = *(const float4*)&B[(n0 + lr) * K + k0 + lc];
        As[lc + 0][lr] = av.x; As[lc + 1][lr] = av.y;
        As[lc + 2][lr] = av.z; As[lc + 3][lr] = av.w;
        Bs[lc + 0][lr] = bv.x; Bs[lc + 1][lr] = bv.y;
        Bs[lc + 2][lr] = bv.z; Bs[lc + 3][lr] = bv.w;
        __syncthreads();
        #pragma unroll
        for (int kk = 0; kk < 8; kk++) {
            float a[8], b[8];
            #pragma unroll
            for (int i = 0; i < 4; i++) {
                a[i]     = As[kk][ty * 8 + i];
                a[i + 4] = As[kk][ty * 8 + i + 4];
                b[i]     = Bs[kk][tx * 8 + i];
                b[i + 4] = Bs[kk][tx * 8 + i + 4];
            }
            #pragma unroll
            for (int i = 0; i < 8; i++)
                #pragma unroll
                for (int j = 0; j < 8; j++)
                    acc[i][j] = fmaf(a[i], b[j], acc[i][j]);
        }
        __syncthreads();
    }
    #pragma unroll
    for (int i = 0; i < 8; i++) {
        int row = m0 + ty * 8 + i;
        float4 v0 = make_float4(acc[i][0], acc[i][1], acc[i][2], acc[i][3]);
        float4 v1 = make_float4(acc[i][4], acc[i][5], acc[i][6], acc[i][7]);
        *(float4*)&C[row * N + n0 + tx * 8]     = v0;
        *(float4*)&C[row * N + n0 + tx * 8 + 4] = v1;
    }
}

// ---------------------------------------------------------------------------
// Per (t,h): v residual, RMS-norm(q,k), rotary. 64 threads/block.
// ---------------------------------------------------------------------------
__global__ void postprocess(const float* __restrict__ qkv,
                            const float* __restrict__ ve,
                            const float* __restrict__ q_scale,
                            const float* __restrict__ k_scale,
                            const float* __restrict__ v_lambda,
                            float* __restrict__ Q,
                            float* __restrict__ Kb,
                            float* __restrict__ V) {
    const int t = blockIdx.x, h = blockIdx.y, d = threadIdx.x;
    __shared__ float sq[64], sk[64];
    __shared__ float redq[2], redk[2];

    const int base  = t * 3 * DIM + h * HD + d;
    const int obase = t * DIM + h * HD + d;
    float q = qkv[base];
    float k = qkv[base + DIM];
    float v = qkv[base + 2 * DIM];

    V[obase] = v + softplus_f(*v_lambda) * ve[obase];

    float qs = q * q, ks = k * k;
    #pragma unroll
    for (int off = 16; off > 0; off >>= 1) {
        qs += __shfl_xor_sync(0xffffffffu, qs, off);
        ks += __shfl_xor_sync(0xffffffffu, ks, off);
    }
    int warp = d >> 5;
    if ((d & 31) == 0) { redq[warp] = qs; redk[warp] = ks; }
    __syncthreads();
    float qsum = redq[0] + redq[1];
    float ksum = redk[0] + redk[1];

    const float EPS = 1.1920929e-07f;
    float qn = q * (softplus_f(*q_scale) * 8.0f / (sqrtf(qsum) + EPS));
    float kn = k * (softplus_f(*k_scale) * 8.0f / (sqrtf(ksum) + EPS));
    sq[d] = qn;
    sk[d] = kn;
    __syncthreads();

    if (d < 32) {
        float c = 1.0f, s = 0.0f;
        if (d < 16) {
            float freq  = powf(1.0f / 1024.0f, (float)d * (1.0f / 15.0f));
            float theta = (float)t * freq;
            c = cosf(theta);
            s = sinf(theta);
        }
        float x1q = sq[d], x2q = sq[d + 32];
        float x1k = sk[d], x2k = sk[d + 32];
        int ob = t * DIM + h * HD;
        Q [ob + d]      =  x1q * c + x2q * s;
        Q [ob + d + 32] = -x1q * s + x2q * c;
        Kb[ob + d]      =  x1k * c + x2k * s;
        Kb[ob + d + 32] = -x1k * s + x2k * c;
    }
}

// ---------------------------------------------------------------------------
// Causal flash attention, fp32. Block = (head, 128-query tile), 128 threads,
// one query per thread, 32-key tiles, float4 smem traffic, __expf.
// 32KB static smem (no dynamic smem, no cudaFuncSetAttribute needed).
// c_proj_scale folded into the epilogue.
// ---------------------------------------------------------------------------
#define KT 32
__global__ __launch_bounds__(128) void attn(const float* __restrict__ Q,
                                            const float* __restrict__ K,
                                            const float* __restrict__ V,
                                            const float* __restrict__ c_proj_scale,
                                            float* __restrict__ Y) {
    __shared__ float Ks[KT * 64];    //  8KB
    __shared__ float Vs[KT * 64];    //  8KB
    __shared__ float Ss[KT * 128];   // 16KB, [key][query]

    const int h   = blockIdx.y;
    const int qt  = gridDim.x - 1 - blockIdx.x;   // heavy tiles first
    const int q0  = qt * 128;
    const int tid = threadIdx.x;
    const int qi  = q0 + tid;

    float4 qreg[16];
    const float4* Qp = (const float4*)&Q[qi * DIM + h * HD];
    #pragma unroll
    for (int i = 0; i < 16; i++) qreg[i] = Qp[i];

    float m = -INFINITY, l = 0.0f;
    float4 acc[16];
    #pragma unroll
    for (int i = 0; i < 16; i++) acc[i] = make_float4(0.f, 0.f, 0.f, 0.f);

    const int nkt = (q0 + 128) / KT;   // key tiles covering [0, q0+128)
    for (int kt = 0; kt < nkt; kt++) {
        const int k0 = kt * KT;
        // cooperative tile load: KT rows x 16 float4 each for K and V
        {
            int r = tid >> 4;           // 0..7 -> 4 rows per thread-group pass
            int c = tid & 15;
            #pragma unroll
            for (int rr = 0; rr < KT; rr += 8) {
                ((float4*)Ks)[(rr + r) * 16 + c] =
                    *(const float4*)&K[(k0 + rr + r) * DIM + h * HD + c * 4];
                ((float4*)Vs)[(rr + r) * 16 + c] =
                    *(const float4*)&V[(k0 + rr + r) * DIM + h * HD + c * 4];
            }
        }
        __syncthreads();

        float tmax = -INFINITY;
        const bool full = (k0 + KT - 1 <= q0);    // unmasked for all qi in tile
        if (full) {
            #pragma unroll 2
            for (int kk = 0; kk < KT; kk++) {
                const float4* Kr = (const float4*)(Ks + kk * 64);
                float s = 0.0f;
                #pragma unroll
                for (int i = 0; i < 16; i++) {
                    float4 kv = Kr[i];
                    s = fmaf(qreg[i].x, kv.x, s);
                    s = fmaf(qreg[i].y, kv.y, s);
                    s = fmaf(qreg[i].z, kv.z, s);
                    s = fmaf(qreg[i].w, kv.w, s);
                }
                s *= 0.125f;
                Ss[kk * 128 + tid] = s;
                tmax = fmaxf(tmax, s);
            }
        } else {
            #pragma unroll 2
            for (int kk = 0; kk < KT; kk++) {
                float s = -INFINITY;
                if (k0 + kk <= qi) {
                    const float4* Kr = (const float4*)(Ks + kk * 64);
                    float t = 0.0f;
                    #pragma unroll
                    for (int i = 0; i < 16; i++) {
                        float4 kv = Kr[i];
                        t = fmaf(qreg[i].x, kv.x, t);
                        t = fmaf(qreg[i].y, kv.y, t);
                        t = fmaf(qreg[i].z, kv.z, t);
                        t = fmaf(qreg[i].w, kv.w, t);
                    }
                    s = t * 0.125f;
                }
                Ss[kk * 128 + tid] = s;
                tmax = fmaxf(tmax, s);
            }
        }

        float mnew = fmaxf(m, tmax);
        float corr = __expf(m - mnew);   // 0 on first tile (m=-inf)
        m = mnew;
        l *= corr;
        #pragma unroll
        for (int i = 0; i < 16; i++) {
            acc[i].x *= corr; acc[i].y *= corr;
            acc[i].z *= corr; acc[i].w *= corr;
        }

        #pragma unroll 2
        for (int kk = 0; kk < KT; kk++) {
            float p = __expf(Ss[kk * 128 + tid] - m);  // masked -> 0
            l += p;
            const float4* Vr = (const float4*)(Vs + kk * 64);
            #pragma unroll
            for (int i = 0; i < 16; i++) {
                float4 vv = Vr[i];
                acc[i].x = fmaf(p, vv.x, acc[i].x);
                acc[i].y = fmaf(p, vv.y, acc[i].y);
                acc[i].z = fmaf(p, vv.z, acc[i].z);
                acc[i].w = fmaf(p, vv.w, acc[i].w);
            }
        }
        __syncthreads();
    }

    float inv = 1.0f / l;
    const float4* cps = (const float4*)&c_proj_scale[h * HD];
    float4* Yp = (float4*)&Y[qi * DIM + h * HD];
    #pragma unroll
    for (int i = 0; i < 16; i++) {
        float4 cv = cps[i];
        Yp[i] = make_float4(acc[i].x * inv * cv.x, acc[i].y * inv * cv.y,
                            acc[i].z * inv * cv.z, acc[i].w * inv * cv.w);
    }
}

// ---------------------------------------------------------------------------
extern "C" void kernel_launch(void* const* d_in, const int* in_sizes, int n_in,
                              void* d_out, int out_size) {
    const float* x            = (const float*)d_in[0];
    const float* ve           = (const float*)d_in[1];
    const float* c_q          = (const float*)d_in[2];
    const float* c_k          = (const float*)d_in[3];
    const float* c_v          = (const float*)d_in[4];
    const float* qkv_scale    = (const float*)d_in[5];
    const float* q_scale      = (const float*)d_in[6];
    const float* k_scale      = (const float*)d_in[7];
    const float* v_lambda     = (const float*)d_in[8];
    const float* c_proj       = (const float*)d_in[9];
    const float* c_proj_scale = (const float*)d_in[10];
    float* out = (float*)d_out;

    float *Wqkv, *qkv, *Qb, *Kb, *Vb, *Yb;
    cudaGetSymbolAddress((void**)&Wqkv, g_Wqkv);
    cudaGetSymbolAddress((void**)&qkv,  g_qkv);
    cudaGetSymbolAddress((void**)&Qb,   g_Q);
    cudaGetSymbolAddress((void**)&Kb,   g_K);
    cudaGetSymbolAddress((void**)&Vb,   g_V);
    cudaGetSymbolAddress((void**)&Yb,   g_Y);

    build_wqkv<<<(3 * DIM * DIM) / 256, 256>>>(c_q, c_k, c_v, qkv_scale);

    {   // qkv = x @ Wqkv^T   (2048 x 3072, K=1024)
        dim3 grid(3 * DIM / 128, TSEQ / 128);
        sgemm128<<<grid, 256>>>(x, Wqkv, qkv, TSEQ, 3 * DIM, DIM);
    }
    {
        dim3 grid(TSEQ, NH);
        postprocess<<<grid, 64>>>(qkv, ve, q_scale, k_scale, v_lambda, Qb, Kb, Vb);
    }
    {
        dim3 grid(TSEQ / 128, NH);
        attn<<<grid, 128>>>(Qb, Kb, Vb, c_proj_scale, Yb);
    }
    {   // out = Y @ c_proj^T  (2048 x 1024, K=1024)
        dim3 grid(DIM / 128, TSEQ / 128);
        sgemm128<<<grid, 256>>>(Yb, c_proj, out, TSEQ, DIM, DIM);
    }
}